// round 1
// baseline (speedup 1.0000x reference)
#include <cuda_runtime.h>
#include <cuda_bf16.h>
#include <math.h>

// Problem constants
#define Hh 4
#define Nn 512
#define Dd 64
#define Ee (Nn*Nn)          // 262144 = 2^18
#define HE (Hh*Ee)          // 1048576
#define Kk 64
#define CAND_MAX 65536

// JAX threefry counter scheme: 1 = partitionable (default in jax >= 0.4.36), 0 = legacy split-counter
#define JAX_PARTITIONABLE 1

// ---------------- scratch (static device globals; no allocation) ----------------
__device__ float g_A[Hh*Nn*Dd];        // sender-half node transform (+ b_out folded)
__device__ float g_B[Hh*Nn*Dd];        // receiver-half node transform
__device__ float g_g0[HE];             // gumbel noise channel 0
__device__ float g_g1[HE];             // gumbel noise channel 1
__device__ unsigned g_hist[Hh][2048];
__device__ int g_bstar[Hh];
__device__ int g_cabove[Hh];
__device__ unsigned long long g_cand[Hh][CAND_MAX];
__device__ int g_candn[Hh];

// ---------------- threefry2x32 (JAX-exact) ----------------
__device__ __forceinline__ unsigned rotl32(unsigned x, int r) { return __funnelshift_l(x, x, r); }
__device__ __forceinline__ void tf_round(unsigned &x0, unsigned &x1, int r) {
    x0 += x1; x1 = rotl32(x1, r); x1 ^= x0;
}
__device__ __forceinline__ void threefry2x32(unsigned x0, unsigned x1, unsigned &o0, unsigned &o1) {
    const unsigned k0 = 0u, k1 = 42u;
    const unsigned k2 = k0 ^ k1 ^ 0x1BD11BDAu;
    x0 += k0; x1 += k1;
    tf_round(x0,x1,13); tf_round(x0,x1,15); tf_round(x0,x1,26); tf_round(x0,x1,6);
    x0 += k1; x1 += k2 + 1u;
    tf_round(x0,x1,17); tf_round(x0,x1,29); tf_round(x0,x1,16); tf_round(x0,x1,24);
    x0 += k2; x1 += k0 + 2u;
    tf_round(x0,x1,13); tf_round(x0,x1,15); tf_round(x0,x1,26); tf_round(x0,x1,6);
    x0 += k0; x1 += k1 + 3u;
    tf_round(x0,x1,17); tf_round(x0,x1,29); tf_round(x0,x1,16); tf_round(x0,x1,24);
    x0 += k1; x1 += k2 + 4u;
    tf_round(x0,x1,13); tf_round(x0,x1,15); tf_round(x0,x1,26); tf_round(x0,x1,6);
    x0 += k2; x1 += k0 + 5u;
    o0 = x0; o1 = x1;
}

__device__ __forceinline__ unsigned random_bits_at(unsigned i) {
#if JAX_PARTITIONABLE
    unsigned o0, o1;
    threefry2x32(0u, i, o0, o1);   // count as u64 -> (hi=0, lo=i)
    return o0 ^ o1;
#else
    const unsigned halfS = (unsigned)(HE);   // total = 2*HE, half = HE
    unsigned o0, o1;
    if (i < halfS) { threefry2x32(i, i + halfS, o0, o1); return o0; }
    else           { threefry2x32(i - halfS, i, o0, o1); return o1; }
#endif
}

// g = -log(-log(U + EPS) + EPS), f32-rounded at every step, CR log via double
__device__ __forceinline__ float gumbel_from_bits(unsigned bits) {
    float U  = __uint_as_float((bits >> 9) | 0x3f800000u) - 1.0f;
    float t1 = U + 1e-10f;
    float L1 = (float)log((double)t1);
    float t2 = (0.0f - L1) + 1e-10f;
    float L2 = (float)log((double)t2);
    return 0.0f - L2;
}

// ---------------- kernels ----------------
__global__ void zero_scratch_kernel() {
    int i = blockIdx.x * 256 + threadIdx.x;
    if (i < Hh * 2048) ((unsigned*)g_hist)[i] = 0u;
    if (i < Hh) g_candn[i] = 0;
}

// A[h,n,j] = b_out[j] + sum_k feats[h,n,k]*W_out[k,j] ; B uses W_out[64+k, j]
__global__ __launch_bounds__(128) void node_xform_kernel(const float* __restrict__ feats,
                                                         const float* __restrict__ Wout,
                                                         const float* __restrict__ bout) {
    int row = blockIdx.x;              // h*N + n, 0..2047
    int t = threadIdx.x;               // 0..127
    __shared__ float f[Dd];
    if (t < Dd) f[t] = feats[row * Dd + t];
    __syncthreads();
    int col = t & 63;
    bool isA = (t < 64);
    const float* W = Wout + (isA ? 0 : Dd * Dd);
    float acc = isA ? bout[col] : 0.0f;
#pragma unroll
    for (int k = 0; k < Dd; k++) acc = fmaf(f[k], W[k * Dd + col], acc);
    if (isA) g_A[row * Dd + col] = acc;
    else     g_B[row * Dd + col] = acc;
}

__global__ __launch_bounds__(256) void gumbel_kernel() {
    int j = blockIdx.x * 256 + threadIdx.x;
    if (j >= HE) return;
    unsigned i0 = 2u * (unsigned)j;
    g_g0[j] = gumbel_from_bits(random_bits_at(i0));
    g_g1[j] = gumbel_from_bits(random_bits_at(i0 + 1u));
}

// Per 64x64 (rec x snd) tile per head: d, prob, cm, sparse=0, histogram
__global__ __launch_bounds__(256) void edge_kernel(const float* __restrict__ Wcat,
                                                   const float* __restrict__ bcat,
                                                   float* __restrict__ out) {
    int st = blockIdx.x, rt = blockIdx.y, head = blockIdx.z;
    __shared__ float As[64][65];    // [k][snd]
    __shared__ float Bs[64][65];    // [k][rec]
    __shared__ float wc0[64], wc1[64];
    __shared__ unsigned hist[2048];
    int t = threadIdx.x;
    for (int i = t; i < 2048; i += 256) hist[i] = 0u;
    if (t < 64) { wc0[t] = Wcat[t * 2]; wc1[t] = Wcat[t * 2 + 1]; }
    const float* Abase = g_A + (head * Nn + st * 64) * Dd;
    const float* Bbase = g_B + (head * Nn + rt * 64) * Dd;
    for (int i = t; i < 4096; i += 256) {
        int s = i >> 6, k = i & 63;
        As[k][s] = Abase[i];
        Bs[k][s] = Bbase[i];
    }
    __syncthreads();

    int tx = t & 15, ty = t >> 4;     // tx -> 4 consecutive snds, ty -> 4 consecutive recs
    float acc0[4][4], acc1[4][4];
#pragma unroll
    for (int i = 0; i < 4; i++)
#pragma unroll
        for (int j = 0; j < 4; j++) { acc0[i][j] = 0.f; acc1[i][j] = 0.f; }

#pragma unroll 8
    for (int k = 0; k < 64; k++) {
        float a[4], b[4];
#pragma unroll
        for (int j = 0; j < 4; j++) a[j] = As[k][tx * 4 + j];
#pragma unroll
        for (int i = 0; i < 4; i++) b[i] = Bs[k][ty * 4 + i];
        float w0 = wc0[k], w1 = wc1[k];
#pragma unroll
        for (int i = 0; i < 4; i++)
#pragma unroll
            for (int j = 0; j < 4; j++) {
                float hr = fmaxf(a[j] + b[i], 0.0f);
                acc0[i][j] = fmaf(hr, w0, acc0[i][j]);
                acc1[i][j] = fmaf(hr, w1, acc1[i][j]);
            }
    }

    float bc0 = bcat[0], bc1 = bcat[1];
    int rec0 = rt * 64 + ty * 4;
    int snd0 = st * 64 + tx * 4;
#pragma unroll
    for (int i = 0; i < 4; i++) {
        int e0   = (rec0 + i) * Nn + snd0;     // 4-aligned
        int gidx = head * Ee + e0;
        float4 G0 = *reinterpret_cast<const float4*>(g_g0 + gidx);
        float4 G1 = *reinterpret_cast<const float4*>(g_g1 + gidx);
        float4 cmv, pv, zv;
        zv.x = zv.y = zv.z = zv.w = 0.0f;
        float g0a[4] = {G0.x, G0.y, G0.z, G0.w};
        float g1a[4] = {G1.x, G1.y, G1.z, G1.w};
        float cma[4], pa[4];
#pragma unroll
        for (int j = 0; j < 4; j++) {
            float l0 = acc0[i][j] + bc0;
            float l1 = acc1[i][j] + bc1;
            float m  = fmaxf(l0, l1);
            float e0v = expf(l0 - m);
            float e1v = expf(l1 - m);
            float p = e1v / (e0v + e1v);
            pa[j] = p;
            float s0 = l0 + g0a[j];
            float s1 = l1 + g1a[j];
            cma[j] = (s1 > s0) ? 1.0f : 0.0f;
            atomicAdd(&hist[__float_as_uint(p) >> 21], 1u);
        }
        cmv.x = cma[0]; cmv.y = cma[1]; cmv.z = cma[2]; cmv.w = cma[3];
        pv.x  = pa[0];  pv.y  = pa[1];  pv.z  = pa[2];  pv.w  = pa[3];
        *reinterpret_cast<float4*>(out + gidx)            = cmv;  // connection_matrix
        *reinterpret_cast<float4*>(out + HE + gidx)       = pv;   // connection_prob
        *reinterpret_cast<float4*>(out + 2 * HE + gidx)   = zv;   // sparse_labels init
    }
    __syncthreads();
    for (int i = t; i < 2048; i += 256)
        if (hist[i]) atomicAdd(&g_hist[head][i], hist[i]);
}

// Per head: find threshold bin b* (suffix count >= 64) and count strictly above it
__global__ __launch_bounds__(256) void threshold_kernel() {
    int h = blockIdx.x, t = threadIdx.x;
    __shared__ int s[2048];
    for (int i = t; i < 2048; i += 256) s[i] = (int)g_hist[h][i];
    __syncthreads();
    if (t == 0) {
        int cum = 0;
        for (int b = 2047; b >= 0; b--) {
            int c = s[b];
            if (cum + c >= Kk) { g_bstar[h] = b; g_cabove[h] = cum; break; }
            cum += c;
        }
    }
}

// Mark all elements in bins > b*, collect candidates in bin == b*
__global__ __launch_bounds__(256) void collect_kernel(float* __restrict__ out) {
    int idx = blockIdx.x * 256 + threadIdx.x;
    if (idx >= HE) return;
    int h = idx >> 18;                    // E = 2^18
    unsigned e = (unsigned)(idx & (Ee - 1));
    unsigned bits = __float_as_uint(out[HE + idx]);
    int bin = (int)(bits >> 21);
    int bs = g_bstar[h];
    if (bin > bs) {
        out[2 * HE + idx] = 1.0f;
    } else if (bin == bs) {
        int p = atomicAdd(&g_candn[h], 1);
        if (p < CAND_MAX)
            g_cand[h][p] = (((unsigned long long)bits) << 32) | (unsigned long long)((unsigned)(Ee - 1) - e);
    }
}

// Per head: pick top (64 - cabove) candidates by (value, then smaller index)
__global__ __launch_bounds__(256) void topk_final_kernel(float* __restrict__ out) {
    int h = blockIdx.x, t = threadIdx.x;
    int take = Kk - g_cabove[h];
    int n = g_candn[h]; if (n > CAND_MAX) n = CAND_MAX;
    unsigned long long* cand = g_cand[h];
    __shared__ unsigned long long rbuf[256];
    for (int it = 0; it < take; it++) {
        unsigned long long best = 0ull;
        for (int i = t; i < n; i += 256) { unsigned long long v = cand[i]; if (v > best) best = v; }
        rbuf[t] = best;
        __syncthreads();
        for (int off = 128; off > 0; off >>= 1) {
            if (t < off) { if (rbuf[t + off] > rbuf[t]) rbuf[t] = rbuf[t + off]; }
            __syncthreads();
        }
        unsigned long long win = rbuf[0];
        __syncthreads();
        for (int i = t; i < n; i += 256) if (cand[i] == win) cand[i] = 0ull;
        if (t == 0) {
            unsigned e = (unsigned)(Ee - 1) - (unsigned)(win & 0xffffffffull);
            out[2 * HE + h * Ee + (int)e] = 1.0f;
        }
        __syncthreads();
    }
}

// ---------------- launch ----------------
extern "C" void kernel_launch(void* const* d_in, const int* in_sizes, int n_in,
                              void* d_out, int out_size) {
    const float* feats = (const float*)d_in[0];   // [4,512,64]
    const float* W_out = (const float*)d_in[1];   // [128,64]
    const float* b_out = (const float*)d_in[2];   // [64]
    const float* W_cat = (const float*)d_in[3];   // [64,2]
    const float* b_cat = (const float*)d_in[4];   // [2]
    float* out = (float*)d_out;                   // cm | prob | sparse, each H*E

    zero_scratch_kernel<<<32, 256>>>();
    node_xform_kernel<<<Hh * Nn, 128>>>(feats, W_out, b_out);
    gumbel_kernel<<<HE / 256, 256>>>();
    {
        dim3 grid(Nn / 64, Nn / 64, Hh);
        edge_kernel<<<grid, 256>>>(W_cat, b_cat, out);
    }
    threshold_kernel<<<Hh, 256>>>();
    collect_kernel<<<HE / 256, 256>>>(out);
    topk_final_kernel<<<Hh, 256>>>(out);
}

// round 3
// speedup vs baseline: 6.9789x; 6.9789x over previous
#include <cuda_runtime.h>
#include <cuda_bf16.h>
#include <math.h>

// Problem constants
#define Hh 4
#define Nn 512
#define Dd 64
#define Ee (Nn*Nn)          // 262144 = 2^18
#define HE (Hh*Ee)          // 1048576
#define Kk 64
#define CAND_MAX 16384

// JAX threefry counter scheme: 1 = partitionable (default in jax >= 0.4.36)
#define JAX_PARTITIONABLE 1

// ---------------- scratch (static device globals; no allocation) ----------------
__device__ float g_A[Hh*Nn*Dd];        // sender-half node transform (+ b_out folded)
__device__ float g_B[Hh*Nn*Dd];        // receiver-half node transform
__device__ float g_g0[HE];             // gumbel noise channel 0
__device__ float g_g1[HE];             // gumbel noise channel 1
__device__ unsigned g_hist[Hh][2048];  // level-1 histogram (bits>>21)
__device__ unsigned g_hist2[Hh][2048]; // level-2 histogram ((bits>>10)&2047) within b1*
__device__ int g_bstar[Hh];
__device__ int g_cabove[Hh];
__device__ int g_bstar2[Hh];
__device__ int g_cabove2[Hh];
__device__ unsigned long long g_cand[Hh][CAND_MAX];
__device__ int g_candn[Hh];

// ---------------- threefry2x32 (JAX-exact) ----------------
__device__ __forceinline__ unsigned rotl32(unsigned x, int r) { return __funnelshift_l(x, x, r); }
__device__ __forceinline__ void tf_round(unsigned &x0, unsigned &x1, int r) {
    x0 += x1; x1 = rotl32(x1, r); x1 ^= x0;
}
__device__ __forceinline__ void threefry2x32(unsigned x0, unsigned x1, unsigned &o0, unsigned &o1) {
    const unsigned k0 = 0u, k1 = 42u;
    const unsigned k2 = k0 ^ k1 ^ 0x1BD11BDAu;
    x0 += k0; x1 += k1;
    tf_round(x0,x1,13); tf_round(x0,x1,15); tf_round(x0,x1,26); tf_round(x0,x1,6);
    x0 += k1; x1 += k2 + 1u;
    tf_round(x0,x1,17); tf_round(x0,x1,29); tf_round(x0,x1,16); tf_round(x0,x1,24);
    x0 += k2; x1 += k0 + 2u;
    tf_round(x0,x1,13); tf_round(x0,x1,15); tf_round(x0,x1,26); tf_round(x0,x1,6);
    x0 += k0; x1 += k1 + 3u;
    tf_round(x0,x1,17); tf_round(x0,x1,29); tf_round(x0,x1,16); tf_round(x0,x1,24);
    x0 += k1; x1 += k2 + 4u;
    tf_round(x0,x1,13); tf_round(x0,x1,15); tf_round(x0,x1,26); tf_round(x0,x1,6);
    x0 += k2; x1 += k0 + 5u;
    o0 = x0; o1 = x1;
}

__device__ __forceinline__ unsigned random_bits_at(unsigned i) {
#if JAX_PARTITIONABLE
    unsigned o0, o1;
    threefry2x32(0u, i, o0, o1);
    return o0 ^ o1;
#else
    const unsigned halfS = (unsigned)(HE);
    unsigned o0, o1;
    if (i < halfS) { threefry2x32(i, i + halfS, o0, o1); return o0; }
    else           { threefry2x32(i - halfS, i, o0, o1); return o1; }
#endif
}

// ---------------- double-float (2x f32) natural log, ~2^-45 relative accuracy ----
// Valid for normal positive x (our domain: [1e-10, 24]). FP32 pipe only.
__device__ __forceinline__ float log_df(float x) {
    int ib = __float_as_int(x);
    int e  = (ib - 0x3f3504f3) >> 23;            // m in [sqrt(2)/2, sqrt(2))
    float m = __int_as_float(ib - (e << 23));
    float f = m - 1.0f;                          // exact (Sterbenz)
    // u = 2 + f as hi/lo (Fast2Sum, |2| >= |f|)
    float uh = 2.0f + f;
    float ul = f - (uh - 2.0f);
    // s = f/u as hi/lo via reciprocal + residual correction
    float r  = 1.0f / uh;
    float sh = f * r;
    float t  = fmaf(-sh, uh, f);
    t = fmaf(-sh, ul, t);
    float sl = t * r;                            // s = sh + sl, accurate ~2^-45
    // z = s^2 (hi + small lo)
    float zh = sh * sh;
    float zl = fmaf(sh, sh, -zh) + 2.0f * sh * sl;
    // log(m) = 2s + s*z*C(z),  C(z) = 2/3 + 2/5 z + 2/7 z^2 + 2/9 z^3 + 2/11 z^4
    float C = fmaf(zh, 0.18181818183f, 0.22222222222f);
    C = fmaf(zh, C, 0.28571428571f);
    C = fmaf(zh, C, 0.4f);
    C = fmaf(zh, C, 0.66666666667f);
    float p    = sh * zh;
    float tail = fmaf(p, C, 2.0f * sl);
    tail = fmaf(sh * zl, 0.66666666667f, tail);
    float lh = 2.0f * sh;
    // e*ln2 split (fdlibm constants; exact for |e| < 128)
    float fe = (float)e;
    float A  = fe * 0.69314575195f;              // 0x3f317180, exact
    // Fast2Sum(A, lh): valid (e==0 -> A=0; |e|>=1 -> |A| >= 0.693 > |lh| <= 0.344)
    float rh = A + lh;
    float rl = lh - (rh - A);
    float small = fmaf(fe, 1.4286067653e-06f, tail) + rl;
    return rh + small;
}

// g = -log(-log(U + EPS) + EPS), f32-rounded at every step
__device__ __forceinline__ float gumbel_from_bits(unsigned bits) {
    float U  = __uint_as_float((bits >> 9) | 0x3f800000u) - 1.0f;
    float t1 = U + 1e-10f;
    float L1 = log_df(t1);
    float t2 = (0.0f - L1) + 1e-10f;
    float L2 = log_df(t2);
    return 0.0f - L2;
}

// ---------------- kernels ----------------
__global__ void zero_scratch_kernel() {
    int i = blockIdx.x * 256 + threadIdx.x;
    if (i < Hh * 2048) {
        ((unsigned*)g_hist)[i]  = 0u;
        ((unsigned*)g_hist2)[i] = 0u;
    }
    if (i < Hh) g_candn[i] = 0;
}

// A[h,n,j] = b_out[j] + sum_k feats[h,n,k]*W_out[k,j] ; B uses W_out[64+k, j]
__global__ __launch_bounds__(128) void node_xform_kernel(const float* __restrict__ feats,
                                                         const float* __restrict__ Wout,
                                                         const float* __restrict__ bout) {
    int row = blockIdx.x;
    int t = threadIdx.x;
    __shared__ float f[Dd];
    if (t < Dd) f[t] = feats[row * Dd + t];
    __syncthreads();
    int col = t & 63;
    bool isA = (t < 64);
    const float* W = Wout + (isA ? 0 : Dd * Dd);
    float acc = isA ? bout[col] : 0.0f;
#pragma unroll
    for (int k = 0; k < Dd; k++) acc = fmaf(f[k], W[k * Dd + col], acc);
    if (isA) g_A[row * Dd + col] = acc;
    else     g_B[row * Dd + col] = acc;
}

__global__ __launch_bounds__(256) void gumbel_kernel() {
    int j = blockIdx.x * 256 + threadIdx.x;
    if (j >= HE) return;
    unsigned i0 = 2u * (unsigned)j;
    g_g0[j] = gumbel_from_bits(random_bits_at(i0));
    g_g1[j] = gumbel_from_bits(random_bits_at(i0 + 1u));
}

// Per 64x64 (rec x snd) tile per head: cm, prob, sparse=0, level-1 histogram
__global__ __launch_bounds__(256) void edge_kernel(const float* __restrict__ Wcat,
                                                   const float* __restrict__ bcat,
                                                   float* __restrict__ out) {
    int st = blockIdx.x, rt = blockIdx.y, head = blockIdx.z;
    __shared__ float As[64][65];
    __shared__ float Bs[64][65];
    __shared__ float wc0[64], wc1[64];
    __shared__ unsigned hist[2048];
    int t = threadIdx.x;
    for (int i = t; i < 2048; i += 256) hist[i] = 0u;
    if (t < 64) { wc0[t] = Wcat[t * 2]; wc1[t] = Wcat[t * 2 + 1]; }
    const float* Abase = g_A + (head * Nn + st * 64) * Dd;
    const float* Bbase = g_B + (head * Nn + rt * 64) * Dd;
    for (int i = t; i < 4096; i += 256) {
        int s = i >> 6, k = i & 63;
        As[k][s] = Abase[i];
        Bs[k][s] = Bbase[i];
    }
    __syncthreads();

    int tx = t & 15, ty = t >> 4;
    float acc0[4][4], acc1[4][4];
#pragma unroll
    for (int i = 0; i < 4; i++)
#pragma unroll
        for (int j = 0; j < 4; j++) { acc0[i][j] = 0.f; acc1[i][j] = 0.f; }

#pragma unroll 8
    for (int k = 0; k < 64; k++) {
        float a[4], b[4];
#pragma unroll
        for (int j = 0; j < 4; j++) a[j] = As[k][tx * 4 + j];
#pragma unroll
        for (int i = 0; i < 4; i++) b[i] = Bs[k][ty * 4 + i];
        float w0 = wc0[k], w1 = wc1[k];
#pragma unroll
        for (int i = 0; i < 4; i++)
#pragma unroll
            for (int j = 0; j < 4; j++) {
                float hr = fmaxf(a[j] + b[i], 0.0f);
                acc0[i][j] = fmaf(hr, w0, acc0[i][j]);
                acc1[i][j] = fmaf(hr, w1, acc1[i][j]);
            }
    }

    float bc0 = bcat[0], bc1 = bcat[1];
    int rec0 = rt * 64 + ty * 4;
    int snd0 = st * 64 + tx * 4;
#pragma unroll
    for (int i = 0; i < 4; i++) {
        int e0   = (rec0 + i) * Nn + snd0;
        int gidx = head * Ee + e0;
        float4 G0 = *reinterpret_cast<const float4*>(g_g0 + gidx);
        float4 G1 = *reinterpret_cast<const float4*>(g_g1 + gidx);
        float4 cmv, pv, zv;
        zv.x = zv.y = zv.z = zv.w = 0.0f;
        float g0a[4] = {G0.x, G0.y, G0.z, G0.w};
        float g1a[4] = {G1.x, G1.y, G1.z, G1.w};
        float cma[4], pa[4];
#pragma unroll
        for (int j = 0; j < 4; j++) {
            float l0 = acc0[i][j] + bc0;
            float l1 = acc1[i][j] + bc1;
            float m  = fmaxf(l0, l1);
            float e0v = expf(l0 - m);
            float e1v = expf(l1 - m);
            float p = e1v / (e0v + e1v);
            pa[j] = p;
            float s0 = l0 + g0a[j];
            float s1 = l1 + g1a[j];
            cma[j] = (s1 > s0) ? 1.0f : 0.0f;
            atomicAdd(&hist[__float_as_uint(p) >> 21], 1u);
        }
        cmv.x = cma[0]; cmv.y = cma[1]; cmv.z = cma[2]; cmv.w = cma[3];
        pv.x  = pa[0];  pv.y  = pa[1];  pv.z  = pa[2];  pv.w  = pa[3];
        *reinterpret_cast<float4*>(out + gidx)            = cmv;
        *reinterpret_cast<float4*>(out + HE + gidx)       = pv;
        *reinterpret_cast<float4*>(out + 2 * HE + gidx)   = zv;
    }
    __syncthreads();
    for (int i = t; i < 2048; i += 256)
        if (hist[i]) atomicAdd(&g_hist[head][i], hist[i]);
}

// Parallel suffix-scan threshold: find b* s.t. suffix-count(b > b*) < target <= suffix incl b*
__device__ __forceinline__ void threshold_scan(const unsigned* hist, int target,
                                               int* bstar_out, int* cabove_out) {
    int t = threadIdx.x;
    __shared__ int psum[256];
    int local[8];
    int base = t * 8;
    int ls = 0;
#pragma unroll
    for (int i = 0; i < 8; i++) { local[i] = (int)hist[base + i]; ls += local[i]; }
    psum[t] = ls;
    __syncthreads();
    // inclusive suffix sum over psum
    for (int off = 1; off < 256; off <<= 1) {
        int add = (t + off < 256) ? psum[t + off] : 0;
        __syncthreads();
        psum[t] += add;
        __syncthreads();
    }
    int excl = psum[t] - ls;   // count strictly above this thread's chunk
    int cum = excl;
#pragma unroll
    for (int i = 7; i >= 0; i--) {
        if (cum < target && cum + local[i] >= target) {
            *bstar_out = base + i;
            *cabove_out = cum;
        }
        cum += local[i];
    }
}

__global__ __launch_bounds__(256) void threshold1_kernel() {
    int h = blockIdx.x;
    threshold_scan(g_hist[h], Kk, &g_bstar[h], &g_cabove[h]);
}

// Mark bins > b1*; build level-2 histogram for bin == b1*
__global__ __launch_bounds__(256) void collect1_kernel(float* __restrict__ out) {
    int idx = blockIdx.x * 256 + threadIdx.x;
    if (idx >= HE) return;
    int h = idx >> 18;
    unsigned bits = __float_as_uint(out[HE + idx]);
    int bin = (int)(bits >> 21);
    int bs = g_bstar[h];
    if (bin > bs) {
        out[2 * HE + idx] = 1.0f;
    } else if (bin == bs) {
        atomicAdd(&g_hist2[h][(bits >> 10) & 2047], 1u);
    }
}

__global__ __launch_bounds__(256) void threshold2_kernel() {
    int h = blockIdx.x;
    int rem = Kk - g_cabove[h];
    threshold_scan(g_hist2[h], rem, &g_bstar2[h], &g_cabove2[h]);
}

// Mark level-2 bins > b2*; collect candidates in bin2 == b2*
__global__ __launch_bounds__(256) void collect2_kernel(float* __restrict__ out) {
    int idx = blockIdx.x * 256 + threadIdx.x;
    if (idx >= HE) return;
    int h = idx >> 18;
    unsigned e = (unsigned)(idx & (Ee - 1));
    unsigned bits = __float_as_uint(out[HE + idx]);
    int bin = (int)(bits >> 21);
    if (bin != g_bstar[h]) return;
    int bin2 = (int)((bits >> 10) & 2047);
    int bs2 = g_bstar2[h];
    if (bin2 > bs2) {
        out[2 * HE + idx] = 1.0f;
    } else if (bin2 == bs2) {
        int p = atomicAdd(&g_candn[h], 1);
        if (p < CAND_MAX)
            g_cand[h][p] = (((unsigned long long)bits) << 32)
                         | (unsigned long long)((unsigned)(Ee - 1) - e);
    }
}

// Pick top (K - cabove1 - cabove2) candidates by (value, then smaller index)
__global__ __launch_bounds__(256) void topk_final_kernel(float* __restrict__ out) {
    int h = blockIdx.x, t = threadIdx.x;
    int take = Kk - g_cabove[h] - g_cabove2[h];
    int n = g_candn[h]; if (n > CAND_MAX) n = CAND_MAX;
    __shared__ unsigned long long cs[4096];
    __shared__ unsigned long long wmax[8];
    bool inSmem = (n <= 4096);
    unsigned long long* cand = inSmem ? cs : g_cand[h];
    if (inSmem) for (int i = t; i < n; i += 256) cs[i] = g_cand[h][i];
    __syncthreads();
    for (int it = 0; it < take; it++) {
        unsigned long long best = 0ull;
        for (int i = t; i < n; i += 256) { unsigned long long v = cand[i]; if (v > best) best = v; }
#pragma unroll
        for (int o = 16; o > 0; o >>= 1) {
            unsigned long long v = __shfl_xor_sync(0xffffffffu, best, o);
            if (v > best) best = v;
        }
        if ((t & 31) == 0) wmax[t >> 5] = best;
        __syncthreads();
        unsigned long long win;
        if (t == 0) {
            win = wmax[0];
#pragma unroll
            for (int i = 1; i < 8; i++) if (wmax[i] > win) win = wmax[i];
            wmax[0] = win;
        }
        __syncthreads();
        win = wmax[0];
        for (int i = t; i < n; i += 256) if (cand[i] == win) cand[i] = 0ull;
        if (t == 0) {
            unsigned e = (unsigned)(Ee - 1) - (unsigned)(win & 0xffffffffull);
            out[2 * HE + h * Ee + (int)e] = 1.0f;
        }
        __syncthreads();
    }
}

// ---------------- launch ----------------
extern "C" void kernel_launch(void* const* d_in, const int* in_sizes, int n_in,
                              void* d_out, int out_size) {
    const float* feats = (const float*)d_in[0];
    const float* W_out = (const float*)d_in[1];
    const float* b_out = (const float*)d_in[2];
    const float* W_cat = (const float*)d_in[3];
    const float* b_cat = (const float*)d_in[4];
    float* out = (float*)d_out;

    zero_scratch_kernel<<<32, 256>>>();
    node_xform_kernel<<<Hh * Nn, 128>>>(feats, W_out, b_out);
    gumbel_kernel<<<HE / 256, 256>>>();
    {
        dim3 grid(Nn / 64, Nn / 64, Hh);
        edge_kernel<<<grid, 256>>>(W_cat, b_cat, out);
    }
    threshold1_kernel<<<Hh, 256>>>();
    collect1_kernel<<<HE / 256, 256>>>(out);
    threshold2_kernel<<<Hh, 256>>>();
    collect2_kernel<<<HE / 256, 256>>>(out);
    topk_final_kernel<<<Hh, 256>>>(out);
}